// round 14
// baseline (speedup 1.0000x reference)
#include <cuda_runtime.h>
#include <cstdint>

// Sparsemax along dim=-1 for X[4096, 32000] fp32. Persistent-CTA, fused
// STG|LDS consume with CHUNKED WAITS / BATCHED ISSUE:
//  - row TMA split into 4 x 32KB chunks, 4 mbarriers, all issued together
//    (sequential addresses -> same DRAM stream as one 128KB burst).
//  - consume walks chunks in order: wait(c) -> {store row r | load row r+1}
//    for that chunk; chunk0 is ready ~3/4 service earlier, so consume+solve
//    hide under the stream tail instead of serializing after it.
//  - ONE merged barrier per row (buffer-free + solve S1), re-issue batched.
//  - register layout v[i] <-> row float4 i*1000+t (t<1000) so chunk c covers
//    exactly v[2c], v[2c+1].
//  - tau: support subset of {x > max-1}; count + scans (2 more syncs),
//    all-warp register Newton (no broadcast sync); block-Newton fallback.

#define NTHREADS 1024
#define NVEC     8
#define D        32000
#define D4       8000
#define NCHK     4
#define CHKF     8000           // floats per chunk
#define CHKB     32000u         // bytes per chunk
#define CANDMAX  128

__device__ __forceinline__ unsigned smem_u32(const void* p) {
    return (unsigned)__cvta_generic_to_shared(p);
}

__device__ __forceinline__ float warp_max_f(float v) {
    #pragma unroll
    for (int o = 16; o > 0; o >>= 1)
        v = fmaxf(v, __shfl_xor_sync(0xffffffffu, v, o));
    return v;
}

__device__ __forceinline__ void mbar_wait(unsigned mbar, unsigned ph) {
    asm volatile(
        "{\n\t"
        ".reg .pred P;\n\t"
        "WAIT_%=: \n\t"
        "mbarrier.try_wait.parity.acquire.cta.shared::cta.b64 P, [%0], %1, 0x989680;\n\t"
        "@P bra.uni DONE_%=;\n\t"
        "bra.uni WAIT_%=;\n\t"
        "DONE_%=: \n\t"
        "}\n\t" :: "r"(mbar), "r"(ph) : "memory");
}

__device__ __forceinline__ void tma_chunk(unsigned dst_smem, const float* src,
                                          unsigned mbar) {
    asm volatile("mbarrier.arrive.expect_tx.shared.b64 _, [%0], %1;"
                 :: "r"(mbar), "r"(CHKB) : "memory");
    asm volatile("cp.async.bulk.shared::cluster.global.mbarrier::complete_tx::bytes "
                 "[%0], [%1], %2, [%3];"
                 :: "r"(dst_smem), "l"(src), "r"(CHKB), "r"(mbar) : "memory");
}

__global__ void __launch_bounds__(NTHREADS, 1)
sparsemax_kernel(const float* __restrict__ X, float* __restrict__ Y, int nrows)
{
    __shared__ float s_warpf[32];
    __shared__ int   s_warpi[32];
    __shared__ float s_bcast;
    __shared__ float s_tau;
    __shared__ float s_cand[CANDMAX];
    __shared__ __align__(8) unsigned long long s_mbar[NCHK];

    extern __shared__ float s_dyn[];
    float* s_buf = s_dyn;            // 32000 floats = 128000 B TMA buffer

    const int t    = threadIdx.x;
    const int lane = t & 31;
    const int wid  = t >> 5;
    const int grid = gridDim.x;
    const float NINF = __int_as_float(0xff800000);

    if (t < NCHK)
        asm volatile("mbarrier.init.shared.b64 [%0], 1;"
                     :: "r"(smem_u32(&s_mbar[t])) : "memory");
    __syncthreads();

    int row = blockIdx.x;
    if (row >= nrows) return;
    int next = row + grid;

    // issue all 4 chunks of a row back-to-back (t==0 caller-guarded)
    auto issue_row = [&](long long r) {
        const float* src = X + r * (long long)D;
        #pragma unroll
        for (int c = 0; c < NCHK; c++)
            tma_chunk(smem_u32(s_buf + c * CHKF), src + c * CHKF,
                      smem_u32(&s_mbar[c]));
    };

    float4 v[NVEC];
    #pragma unroll
    for (int i = 0; i < NVEC; i++) v[i] = make_float4(NINF, NINF, NINF, NINF);
    float vmax = NINF;
    float tau;

    // ---- prologue: LDG row0 (layout i*1000+t), TMA row1 --------------------
    if (t < 1000) {
        const float4* src = reinterpret_cast<const float4*>(X) + (long long)row * D4;
        #pragma unroll
        for (int i = 0; i < NVEC; i++) {
            v[i] = src[i * 1000 + t];
            vmax = fmaxf(vmax, fmaxf(fmaxf(v[i].x, v[i].y), fmaxf(v[i].z, v[i].w)));
        }
    }
    if (t == 0 && next < nrows) issue_row(next);
    unsigned ph = 0;

    // S1-equivalent for prologue
    {
        float wm = warp_max_f(vmax);
        if (lane == 0) s_warpf[wid] = wm;
    }
    __syncthreads();

    // ============ tau solve (expects s_warpf filled + barrier done) =========
    #define SOLVE_TAU()                                                        \
    do {                                                                       \
        const float tau0 = warp_max_f(s_warpf[lane]) - 1.0f;                   \
        int cnt = 0;                                                           \
        _Pragma("unroll")                                                      \
        for (int i = 0; i < NVEC; i++)                                         \
            cnt += (v[i].x > tau0) + (v[i].y > tau0) +                         \
                   (v[i].z > tau0) + (v[i].w > tau0);                          \
        int inc = cnt;                                                         \
        _Pragma("unroll")                                                      \
        for (int o = 1; o < 32; o <<= 1) {                                     \
            int y = __shfl_up_sync(0xffffffffu, inc, o);                       \
            if (lane >= o) inc += y;                                           \
        }                                                                      \
        if (lane == 31) s_warpi[wid] = inc;                                    \
        __syncthreads();                                      /* S2 */         \
        int wt = s_warpi[lane];                                                \
        int wx = wt;                                                           \
        _Pragma("unroll")                                                      \
        for (int o = 1; o < 32; o <<= 1) {                                     \
            int y = __shfl_up_sync(0xffffffffu, wx, o);                        \
            if (lane >= o) wx += y;                                            \
        }                                                                      \
        const int total  = __shfl_sync(0xffffffffu, wx, 31);                   \
        const int mybase = __shfl_sync(0xffffffffu, wx - wt, wid);             \
        if (total <= CANDMAX) {                                                \
            if (cnt) {                                                         \
                int off = mybase + (inc - cnt);                                \
                _Pragma("unroll")                                              \
                for (int i = 0; i < NVEC; i++) {                               \
                    if (v[i].x > tau0) s_cand[off++] = v[i].x;                 \
                    if (v[i].y > tau0) s_cand[off++] = v[i].y;                 \
                    if (v[i].z > tau0) s_cand[off++] = v[i].z;                 \
                    if (v[i].w > tau0) s_cand[off++] = v[i].w;                 \
                }                                                              \
            }                                                                  \
            __syncthreads();                                  /* S3 */         \
            float c0 = (lane      < total) ? s_cand[lane]      : NINF;         \
            float c1 = (lane + 32 < total) ? s_cand[lane + 32] : NINF;         \
            float c2 = (lane + 64 < total) ? s_cand[lane + 64] : NINF;         \
            float c3 = (lane + 96 < total) ? s_cand[lane + 96] : NINF;         \
            float tt = tau0;                                                   \
            for (int it = 0; it < 64; it++) {                                  \
                float s = 0.0f; int k = 0;                                     \
                if (c0 > tt) { s += c0; k++; }                                 \
                if (c1 > tt) { s += c1; k++; }                                 \
                if (c2 > tt) { s += c2; k++; }                                 \
                if (c3 > tt) { s += c3; k++; }                                 \
                _Pragma("unroll")                                              \
                for (int o = 16; o > 0; o >>= 1) {                             \
                    s += __shfl_xor_sync(0xffffffffu, s, o);                   \
                    k += __shfl_xor_sync(0xffffffffu, k, o);                   \
                }                                                              \
                float nt = (s - 1.0f) / (float)k;     /* k>=1 always */        \
                if (nt == tt) break;                                           \
                tt = nt;                                                       \
            }                                                                  \
            tau = tt;                                                          \
        } else {                                                               \
            float tt = s_warpf[0]; tt = tau0;                                  \
            for (int it = 0; it < 64; it++) {                                  \
                float s = 0.0f; int k = 0;                                     \
                _Pragma("unroll")                                              \
                for (int i = 0; i < NVEC; i++) {                               \
                    if (v[i].x > tt) { s += v[i].x; k++; }                     \
                    if (v[i].y > tt) { s += v[i].y; k++; }                     \
                    if (v[i].z > tt) { s += v[i].z; k++; }                     \
                    if (v[i].w > tt) { s += v[i].w; k++; }                     \
                }                                                              \
                _Pragma("unroll")                                              \
                for (int o = 16; o > 0; o >>= 1) {                             \
                    s += __shfl_xor_sync(0xffffffffu, s, o);                   \
                    k += __shfl_xor_sync(0xffffffffu, k, o);                   \
                }                                                              \
                if (lane == 0) { s_warpf[wid] = s; s_warpi[wid] = k; }         \
                __syncthreads();                                               \
                if (t == 0) {                                                  \
                    float S = 0.0f; int K = 0;                                 \
                    _Pragma("unroll")                                          \
                    for (int w = 0; w < 32; w++) { S += s_warpf[w]; K += s_warpi[w]; } \
                    s_bcast = (S - 1.0f) / (float)K;                           \
                }                                                              \
                __syncthreads();                                               \
                float nt = s_bcast;                                            \
                if (nt == tt) break;     /* uniform exit */                    \
                tt = nt;                                                       \
            }                                                                  \
            if (t == 0) s_tau = tt;                                            \
            __syncthreads();                                                   \
            tau = s_tau;                                                       \
        }                                                                      \
    } while (0)

    SOLVE_TAU();   // tau(row 0)

    for (;;) {
        float4* dst = reinterpret_cast<float4*>(Y) + (long long)row * D4;

        if (next >= nrows) {
            // epilogue: stores only
            if (t < 1000) {
                #pragma unroll
                for (int i = 0; i < NVEC; i++) {
                    float4 o;
                    o.x = fmaxf(v[i].x - tau, 0.0f);
                    o.y = fmaxf(v[i].y - tau, 0.0f);
                    o.z = fmaxf(v[i].z - tau, 0.0f);
                    o.w = fmaxf(v[i].w - tau, 0.0f);
                    dst[i * 1000 + t] = o;
                }
            }
            break;
        }

        // ---- chunked consume: wait(c) -> {STG row r | LDS row r+1} ---------
        float vnew = NINF;
        const float4* sb4 = reinterpret_cast<const float4*>(s_buf);
        #pragma unroll
        for (int c = 0; c < NCHK; c++) {
            mbar_wait(smem_u32(&s_mbar[c]), ph);
            if (t < 1000) {
                #pragma unroll
                for (int ii = 0; ii < 2; ii++) {
                    const int i = 2 * c + ii;
                    float4 o;
                    o.x = fmaxf(v[i].x - tau, 0.0f);
                    o.y = fmaxf(v[i].y - tau, 0.0f);
                    o.z = fmaxf(v[i].z - tau, 0.0f);
                    o.w = fmaxf(v[i].w - tau, 0.0f);
                    float4 x = sb4[i * 1000 + t];   // LDS overlaps STG
                    dst[i * 1000 + t] = o;
                    v[i] = x;
                    vnew = fmaxf(vnew, fmaxf(fmaxf(x.x, x.y), fmaxf(x.z, x.w)));
                }
            }
        }
        ph ^= 1u;

        // ---- merged barrier: buffer-free + solve S1 -------------------------
        {
            float wm = warp_max_f(vnew);
            if (lane == 0) s_warpf[wid] = wm;
        }
        __syncthreads();

        // ---- batched re-issue for row next+grid ------------------------------
        {
            int nn = next + grid;
            if (t == 0 && nn < nrows) issue_row(nn);
            row = next;
            next = nn;
        }

        // ---- solve tau(new row); overlaps store drain + inbound TMA ---------
        SOLVE_TAU();
    }
}

extern "C" void kernel_launch(void* const* d_in, const int* in_sizes, int n_in,
                              void* d_out, int out_size)
{
    const float* X = (const float*)d_in[0];
    float* Y = (float*)d_out;
    int rows = in_sizes[0] / D;                 // 4096

    int sms = 148;
    cudaDeviceGetAttribute(&sms, cudaDevAttrMultiProcessorCount, 0);
    int grid = (rows < sms) ? rows : sms;       // persistent: one CTA per SM

    size_t dyn = (size_t)D * sizeof(float);     // 128000 B
    cudaFuncSetAttribute(sparsemax_kernel,
                         cudaFuncAttributeMaxDynamicSharedMemorySize, (int)dyn);
    sparsemax_kernel<<<grid, NTHREADS, dyn>>>(X, Y, rows);
}

// round 15
// speedup vs baseline: 1.0645x; 1.0645x over previous
#include <cuda_runtime.h>
#include <cstdint>

// Sparsemax along dim=-1 for X[4096, 32000] fp32. Persistent-CTA, R13 fused
// schedule + 2.5-buffer split so the DRAM read queue is never empty:
//  - row = H0 (64KB, ping-pong A0/A1) + H1 (64KB, fixed buffer B).
//  - top of iter r: issue H0(r+2) into the A-buffer consumed LAST iteration
//    (free, behind the merged barrier) -> reads stream during consume+solve.
//  - then: wait A -> {STG|LDS v[0..3]} -> wait B -> {STG|LDS v[4..7]} ->
//    merged barrier (S1) -> issue H1(r+2) into B -> solve tau(r+1).
//  - tau: support subset of {x > max-1}; count + warp scans; scattered
//    candidate writes; all-warp register Newton (no broadcast sync);
//    block-Newton fallback. 3 syncs/row. No __stcs / L2 prefetch / LDG tail.

#define NTHREADS 1024
#define NVEC     8
#define D        32000
#define D4       8000
#define HF       16000          // floats per half row
#define HB       64000u         // bytes per half row
#define CANDMAX  128

__device__ __forceinline__ unsigned smem_u32(const void* p) {
    return (unsigned)__cvta_generic_to_shared(p);
}

__device__ __forceinline__ float warp_max_f(float v) {
    #pragma unroll
    for (int o = 16; o > 0; o >>= 1)
        v = fmaxf(v, __shfl_xor_sync(0xffffffffu, v, o));
    return v;
}

__device__ __forceinline__ void mbar_wait(unsigned mbar, unsigned ph) {
    asm volatile(
        "{\n\t"
        ".reg .pred P;\n\t"
        "WAIT_%=: \n\t"
        "mbarrier.try_wait.parity.acquire.cta.shared::cta.b64 P, [%0], %1, 0x989680;\n\t"
        "@P bra.uni DONE_%=;\n\t"
        "bra.uni WAIT_%=;\n\t"
        "DONE_%=: \n\t"
        "}\n\t" :: "r"(mbar), "r"(ph) : "memory");
}

__device__ __forceinline__ void tma_half(unsigned dst_smem, const float* src,
                                         unsigned mbar) {
    asm volatile("mbarrier.arrive.expect_tx.shared.b64 _, [%0], %1;"
                 :: "r"(mbar), "r"(HB) : "memory");
    asm volatile("cp.async.bulk.shared::cluster.global.mbarrier::complete_tx::bytes "
                 "[%0], [%1], %2, [%3];"
                 :: "r"(dst_smem), "l"(src), "r"(HB), "r"(mbar) : "memory");
}

__global__ void __launch_bounds__(NTHREADS, 1)
sparsemax_kernel(const float* __restrict__ X, float* __restrict__ Y, int nrows)
{
    __shared__ float s_warpf[32];
    __shared__ int   s_warpi[32];
    __shared__ float s_bcast;
    __shared__ float s_tau;
    __shared__ float s_cand[CANDMAX];
    __shared__ __align__(8) unsigned long long s_mbar[3];   // A0, A1, B

    extern __shared__ float s_dyn[];
    // A0 = s_dyn, A1 = s_dyn+HF, B = s_dyn+2*HF   (3 x 64KB = 192KB)

    const int t    = threadIdx.x;
    const int lane = t & 31;
    const int wid  = t >> 5;
    const int grid = gridDim.x;
    const float NINF = __int_as_float(0xff800000);

    if (t < 3)
        asm volatile("mbarrier.init.shared.b64 [%0], 1;"
                     :: "r"(smem_u32(&s_mbar[t])) : "memory");
    __syncthreads();

    long long row = blockIdx.x;
    if (row >= nrows) return;
    long long next = row + grid;

    float4 v[NVEC];
    #pragma unroll
    for (int i = 0; i < NVEC; i++) v[i] = make_float4(NINF, NINF, NINF, NINF);
    float vmax = NINF;
    float tau;
    unsigned phbits = 0;     // expected parity per mbarrier, flip after wait
    int abuf = 1;            // H0(next) resides in A[abuf]

    // ---- prologue: LDG row0 (layout i*1000+t); TMA H0(1)->A1, H1(1)->B -----
    if (t < 1000) {
        const float4* src = reinterpret_cast<const float4*>(X) + row * D4;
        #pragma unroll
        for (int i = 0; i < NVEC; i++) {
            v[i] = src[i * 1000 + t];
            vmax = fmaxf(vmax, fmaxf(fmaxf(v[i].x, v[i].y), fmaxf(v[i].z, v[i].w)));
        }
    }
    if (t == 0 && next < nrows) {
        const float* src = X + next * (long long)D;
        tma_half(smem_u32(s_dyn + 1 * HF), src,      smem_u32(&s_mbar[1]));
        tma_half(smem_u32(s_dyn + 2 * HF), src + HF, smem_u32(&s_mbar[2]));
    }

    // S1 for row 0
    {
        float wm = warp_max_f(vmax);
        if (lane == 0) s_warpf[wid] = wm;
    }
    __syncthreads();

    // ============ tau solve (expects s_warpf filled + barrier done) =========
    #define SOLVE_TAU()                                                        \
    do {                                                                       \
        const float tau0 = warp_max_f(s_warpf[lane]) - 1.0f;                   \
        int cnt = 0;                                                           \
        _Pragma("unroll")                                                      \
        for (int i = 0; i < NVEC; i++)                                         \
            cnt += (v[i].x > tau0) + (v[i].y > tau0) +                         \
                   (v[i].z > tau0) + (v[i].w > tau0);                          \
        int inc = cnt;                                                         \
        _Pragma("unroll")                                                      \
        for (int o = 1; o < 32; o <<= 1) {                                     \
            int y = __shfl_up_sync(0xffffffffu, inc, o);                       \
            if (lane >= o) inc += y;                                           \
        }                                                                      \
        if (lane == 31) s_warpi[wid] = inc;                                    \
        __syncthreads();                                      /* S2 */         \
        int wt = s_warpi[lane];                                                \
        int wx = wt;                                                           \
        _Pragma("unroll")                                                      \
        for (int o = 1; o < 32; o <<= 1) {                                     \
            int y = __shfl_up_sync(0xffffffffu, wx, o);                        \
            if (lane >= o) wx += y;                                            \
        }                                                                      \
        const int total  = __shfl_sync(0xffffffffu, wx, 31);                   \
        const int mybase = __shfl_sync(0xffffffffu, wx - wt, wid);             \
        if (total <= CANDMAX) {                                                \
            if (cnt) {                                                         \
                int off = mybase + (inc - cnt);                                \
                _Pragma("unroll")                                              \
                for (int i = 0; i < NVEC; i++) {                               \
                    if (v[i].x > tau0) s_cand[off++] = v[i].x;                 \
                    if (v[i].y > tau0) s_cand[off++] = v[i].y;                 \
                    if (v[i].z > tau0) s_cand[off++] = v[i].z;                 \
                    if (v[i].w > tau0) s_cand[off++] = v[i].w;                 \
                }                                                              \
            }                                                                  \
            __syncthreads();                                  /* S3 */         \
            float c0 = (lane      < total) ? s_cand[lane]      : NINF;         \
            float c1 = (lane + 32 < total) ? s_cand[lane + 32] : NINF;         \
            float c2 = (lane + 64 < total) ? s_cand[lane + 64] : NINF;         \
            float c3 = (lane + 96 < total) ? s_cand[lane + 96] : NINF;         \
            float tt = tau0;                                                   \
            for (int it = 0; it < 64; it++) {                                  \
                float s = 0.0f; int k = 0;                                     \
                if (c0 > tt) { s += c0; k++; }                                 \
                if (c1 > tt) { s += c1; k++; }                                 \
                if (c2 > tt) { s += c2; k++; }                                 \
                if (c3 > tt) { s += c3; k++; }                                 \
                _Pragma("unroll")                                              \
                for (int o = 16; o > 0; o >>= 1) {                             \
                    s += __shfl_xor_sync(0xffffffffu, s, o);                   \
                    k += __shfl_xor_sync(0xffffffffu, k, o);                   \
                }                                                              \
                float nt = (s - 1.0f) / (float)k;     /* k>=1 always */        \
                if (nt == tt) break;                                           \
                tt = nt;                                                       \
            }                                                                  \
            tau = tt;                                                          \
        } else {                                                               \
            float tt = tau0;                                                   \
            for (int it = 0; it < 64; it++) {                                  \
                float s = 0.0f; int k = 0;                                     \
                _Pragma("unroll")                                              \
                for (int i = 0; i < NVEC; i++) {                               \
                    if (v[i].x > tt) { s += v[i].x; k++; }                     \
                    if (v[i].y > tt) { s += v[i].y; k++; }                     \
                    if (v[i].z > tt) { s += v[i].z; k++; }                     \
                    if (v[i].w > tt) { s += v[i].w; k++; }                     \
                }                                                              \
                _Pragma("unroll")                                              \
                for (int o = 16; o > 0; o >>= 1) {                             \
                    s += __shfl_xor_sync(0xffffffffu, s, o);                   \
                    k += __shfl_xor_sync(0xffffffffu, k, o);                   \
                }                                                              \
                if (lane == 0) { s_warpf[wid] = s; s_warpi[wid] = k; }         \
                __syncthreads();                                               \
                if (t == 0) {                                                  \
                    float S = 0.0f; int K = 0;                                 \
                    _Pragma("unroll")                                          \
                    for (int w = 0; w < 32; w++) { S += s_warpf[w]; K += s_warpi[w]; } \
                    s_bcast = (S - 1.0f) / (float)K;                           \
                }                                                              \
                __syncthreads();                                               \
                float nt = s_bcast;                                            \
                if (nt == tt) break;     /* uniform exit */                    \
                tt = nt;                                                       \
            }                                                                  \
            if (t == 0) s_tau = tt;                                            \
            __syncthreads();                                                   \
            tau = s_tau;                                                       \
        }                                                                      \
    } while (0)

    SOLVE_TAU();   // tau(row 0)

    for (;;) {
        float4* dst = reinterpret_cast<float4*>(Y) + row * D4;

        if (next >= nrows) {
            // epilogue: stores only
            if (t < 1000) {
                #pragma unroll
                for (int i = 0; i < NVEC; i++) {
                    float4 o;
                    o.x = fmaxf(v[i].x - tau, 0.0f);
                    o.y = fmaxf(v[i].y - tau, 0.0f);
                    o.z = fmaxf(v[i].z - tau, 0.0f);
                    o.w = fmaxf(v[i].w - tau, 0.0f);
                    dst[i * 1000 + t] = o;
                }
            }
            break;
        }

        const long long nn = next + grid;

        // ---- 0) TOP: issue H0(nn) into the A-buffer freed last iteration ----
        if (t == 0 && nn < nrows)
            tma_half(smem_u32(s_dyn + (abuf ^ 1) * HF),
                     X + nn * (long long)D, smem_u32(&s_mbar[abuf ^ 1]));

        float vnew = NINF;

        // ---- 1) consume H0(next) from A[abuf]: {STG row | LDS next} ---------
        mbar_wait(smem_u32(&s_mbar[abuf]), (phbits >> abuf) & 1u);
        phbits ^= 1u << abuf;
        if (t < 1000) {
            const float4* b4 = reinterpret_cast<const float4*>(s_dyn + abuf * HF);
            #pragma unroll
            for (int i = 0; i < 4; i++) {
                float4 o;
                o.x = fmaxf(v[i].x - tau, 0.0f);
                o.y = fmaxf(v[i].y - tau, 0.0f);
                o.z = fmaxf(v[i].z - tau, 0.0f);
                o.w = fmaxf(v[i].w - tau, 0.0f);
                float4 x = b4[i * 1000 + t];      // LDS overlaps STG
                dst[i * 1000 + t] = o;
                v[i] = x;
                vnew = fmaxf(vnew, fmaxf(fmaxf(x.x, x.y), fmaxf(x.z, x.w)));
            }
        }

        // ---- 2) consume H1(next) from B: {STG row | LDS next} ---------------
        mbar_wait(smem_u32(&s_mbar[2]), (phbits >> 2) & 1u);
        phbits ^= 1u << 2;
        if (t < 1000) {
            const float4* b4 = reinterpret_cast<const float4*>(s_dyn + 2 * HF);
            #pragma unroll
            for (int i = 4; i < NVEC; i++) {
                float4 o;
                o.x = fmaxf(v[i].x - tau, 0.0f);
                o.y = fmaxf(v[i].y - tau, 0.0f);
                o.z = fmaxf(v[i].z - tau, 0.0f);
                o.w = fmaxf(v[i].w - tau, 0.0f);
                float4 x = b4[(i - 4) * 1000 + t];
                dst[i * 1000 + t] = o;
                v[i] = x;
                vnew = fmaxf(vnew, fmaxf(fmaxf(x.x, x.y), fmaxf(x.z, x.w)));
            }
        }

        // ---- 3) merged barrier: buffers free + solve S1 ----------------------
        {
            float wm = warp_max_f(vnew);
            if (lane == 0) s_warpf[wid] = wm;
        }
        __syncthreads();

        // ---- 4) issue H1(nn) into B (just freed) -----------------------------
        if (t == 0 && nn < nrows)
            tma_half(smem_u32(s_dyn + 2 * HF),
                     X + nn * (long long)D + HF, smem_u32(&s_mbar[2]));

        row = next;
        next = nn;
        abuf ^= 1;

        // ---- 5) solve tau(row); overlaps store drain + inbound TMA ----------
        SOLVE_TAU();
    }
}

extern "C" void kernel_launch(void* const* d_in, const int* in_sizes, int n_in,
                              void* d_out, int out_size)
{
    const float* X = (const float*)d_in[0];
    float* Y = (float*)d_out;
    int rows = in_sizes[0] / D;                 // 4096

    int sms = 148;
    cudaDeviceGetAttribute(&sms, cudaDevAttrMultiProcessorCount, 0);
    int grid = (rows < sms) ? rows : sms;       // persistent: one CTA per SM

    size_t dyn = (size_t)(3 * HF) * sizeof(float);   // 192000 B
    cudaFuncSetAttribute(sparsemax_kernel,
                         cudaFuncAttributeMaxDynamicSharedMemorySize, (int)dyn);
    sparsemax_kernel<<<grid, NTHREADS, dyn>>>(X, Y, rows);
}